// round 4
// baseline (speedup 1.0000x reference)
#include <cuda_runtime.h>
#include <cstdint>

#define NN 1024
#define DD 256
#define HH 32
#define OUTS 64
#define NBINS 65

#define TI 16          // i rows per tile
#define TJ 8           // j cols per tile
#define TR 128         // pairs per tile
#define SP 132         // sP pitch (128 rows + pad, 16B aligned)

// scratch for projections (device globals: no allocation allowed)
__device__ float g_left[NN * HH];
__device__ float g_right[NN * HH];

// ---------------------------------------------------------------------------
__device__ __forceinline__ void fma2(unsigned long long& d,
                                     unsigned long long a,
                                     unsigned long long b) {
    asm("fma.rn.f32x2 %0, %1, %2, %0;" : "+l"(d) : "l"(a), "l"(b));
}
__device__ __forceinline__ float2 up2(unsigned long long a) {
    float2 f;
    asm("mov.b64 {%0, %1}, %2;" : "=f"(f.x), "=f"(f.y) : "l"(a));
    return f;
}

// JAX approximate (tanh) GELU; tanh(u) = 1 - 2/(1+exp(2u))
__device__ __forceinline__ float gelu_tanh(float x) {
    float u = 0.7978845608028654f * (x + 0.044715f * x * x * x);
    float e = __expf(2.0f * u);
    float t = 1.0f - __fdividef(2.0f, 1.0f + e);
    return 0.5f * x * (1.0f + t);
}

// ---------------------------------------------------------------------------
// Projection: left = local @ W_left, right = local @ W_right  [1024,256]@[256,32]
// ---------------------------------------------------------------------------
__global__ void proj_kernel(const float* __restrict__ local,
                            const float* __restrict__ Wl,
                            const float* __restrict__ Wr) {
    int idx  = blockIdx.x * blockDim.x + threadIdx.x;
    int h    = idx & 31;
    int n    = (idx >> 5) & (NN - 1);
    int side = idx >> 15;
    const float* W = side ? Wr : Wl;
    float*       g = side ? g_right : g_left;

    const float4* row4 = reinterpret_cast<const float4*>(local + (size_t)n * DD);
    float acc = 0.f;
#pragma unroll
    for (int d4 = 0; d4 < DD / 4; ++d4) {
        float4 r = row4[d4];
        int d = d4 * 4;
        acc += r.x * W[(d + 0) * HH + h];
        acc += r.y * W[(d + 1) * HH + h];
        acc += r.z * W[(d + 2) * HH + h];
        acc += r.w * W[(d + 3) * HH + h];
    }
    g[n * HH + h] = acc;
}

// ---------------------------------------------------------------------------
// Shared memory layout (floats) — dynamic. Weights stored DUPLICATED:
// sWhD[k][2c],[2c+1] = Wh[k][c]  -> packed f32x2 B operands load directly.
// ---------------------------------------------------------------------------
#define OFF_WHD  0                        // 32*64  = 2048
#define OFF_WOD  (OFF_WHD + 2048)         // 32*128 = 4096
#define OFF_REL  (OFF_WOD + 4096)         // 65*36  = 2340
#define OFF_L    (OFF_REL + 2340)         // 16*36  = 576
#define OFF_R    (OFF_L + 576)            // 8*36   = 288
#define OFF_SC   (OFF_R + 288)            // 32
#define OFF_OF   (OFF_SC + 32)            // 32
#define OFF_PM   (OFF_OF + 32)            // 128 (int)
#define OFF_P    (OFF_PM + 128)           // 32*SP = 4224  (aliased: pair, then hidden)
#define SMEM_FLOATS (OFF_P + 32 * SP)
#define SMEM_BYTES  (SMEM_FLOATS * 4)

// ---------------------------------------------------------------------------
// Fused pair kernel: 16x8-pair tiles, 256 threads, 4 CTAs/SM
// ---------------------------------------------------------------------------
__global__ __launch_bounds__(256, 4)
void pair_kernel(const int* __restrict__ resi,
                 const int* __restrict__ chain,
                 const int* __restrict__ batch,
                 const int* __restrict__ mask,
                 const float* __restrict__ W_relpos,
                 const float* __restrict__ ln_scale,
                 const float* __restrict__ ln_offset,
                 const float* __restrict__ W_hidden,
                 const float* __restrict__ W_out,
                 float* __restrict__ out) {
    extern __shared__ float sm[];
    float* sWhD = sm + OFF_WHD;
    float* sWoD = sm + OFF_WOD;
    float* sRel = sm + OFF_REL;
    float* sL   = sm + OFF_L;
    float* sR   = sm + OFF_R;
    float* sSc  = sm + OFF_SC;
    float* sOf  = sm + OFF_OF;
    int*   sPM  = (int*)(sm + OFF_PM);
    float* sP   = sm + OFF_P;

    const int t  = threadIdx.x;
    const int i0 = blockIdx.y * TI, j0 = blockIdx.x * TJ;

    // GEMM2 / store mapping: 8 rows x 4 cols per thread
    const int rg2 = t >> 4;          // 0..15 -> rows rg2*8..+7
    const int cg2 = t & 15;          // 0..15 -> cols cg2*4..+3

    // ---- per-pair mask; block-level early exit ----
    bool pm = false;
    if (t < TR) {
        const int i = i0 + (t >> 3), j = j0 + (t & 7);
        pm = (batch[i] == batch[j]) && (mask[i] != 0) && (mask[j] != 0);
        sPM[t] = pm;
    }
    const int any = __syncthreads_or((int)pm);
    if (!any) {
        const float4 z = make_float4(0.f, 0.f, 0.f, 0.f);
#pragma unroll
        for (int r8 = 0; r8 < 8; ++r8) {
            const int ii = i0 + rg2, jj = j0 + r8;  // row = rg2*8+r8 -> i=i0+rg2, j=j0+r8
            __stcs(reinterpret_cast<float4*>(
                       out + ((size_t)(ii * NN + jj)) * OUTS + cg2 * 4), z);
        }
        return;
    }

    // ---- stage weights (duplicated), rel table, tiles ----
    for (int idx = t; idx < HH * 2 * HH; idx += 256) {         // 2048
        int k = idx >> 6, c = (idx & 63) >> 1;
        sWhD[idx] = W_hidden[k * HH + c];
    }
    for (int idx = t; idx < HH * 2 * OUTS; idx += 256) {       // 4096
        int k = idx >> 7, c = (idx & 127) >> 1;
        sWoD[idx] = W_out[k * OUTS + c];
    }
    for (int idx = t; idx < NBINS * HH; idx += 256)
        sRel[(idx >> 5) * 36 + (idx & 31)] = W_relpos[idx];
    for (int idx = t; idx < TI * HH; idx += 256)
        sL[(idx >> 5) * 36 + (idx & 31)] = g_left[(i0 + (idx >> 5)) * HH + (idx & 31)];
    for (int idx = t; idx < TJ * HH; idx += 256)
        sR[(idx >> 5) * 36 + (idx & 31)] = g_right[(j0 + (idx >> 5)) * HH + (idx & 31)];
    if (t < HH) { sSc[t] = ln_scale[t]; sOf[t] = ln_offset[t]; }
    __syncthreads();

    // ---- Phase A: build pair vector + layernorm (threads 0..127) ----
    if (t < TR) {
        const int i = i0 + (t >> 3), j = j0 + (t & 7);
        const bool same_chain = (batch[i] == batch[j]) && (chain[i] == chain[j]);
        int diff = resi[i] - resi[j];
        diff = min(max(diff, -32), 32) + 32;

        const float* lrow   = &sL[(t >> 3) * 36];
        const float* rrow   = &sR[(t & 7) * 36];
        const float* relrow = &sRel[diff * 36];

        float p[HH];
        float mu = 0.f;
#pragma unroll
        for (int h4 = 0; h4 < 8; ++h4) {
            float4 l = *reinterpret_cast<const float4*>(lrow + h4 * 4);
            float4 r = *reinterpret_cast<const float4*>(rrow + h4 * 4);
            float4 e = *reinterpret_cast<const float4*>(relrow + h4 * 4);
            float4 v;
            v.x = l.x + r.x; v.y = l.y + r.y; v.z = l.z + r.z; v.w = l.w + r.w;
            if (same_chain) { v.x += e.x; v.y += e.y; v.z += e.z; v.w += e.w; }
            p[h4 * 4 + 0] = v.x; p[h4 * 4 + 1] = v.y;
            p[h4 * 4 + 2] = v.z; p[h4 * 4 + 3] = v.w;
            mu += v.x + v.y + v.z + v.w;
        }
        mu *= (1.f / HH);
        float var = 0.f;
#pragma unroll
        for (int h = 0; h < HH; ++h) { float d = p[h] - mu; var += d * d; }
        var *= (1.f / HH);
        const float rstd = rsqrtf(var + 1e-5f);
#pragma unroll
        for (int h = 0; h < HH; ++h)
            sP[h * SP + t] = (p[h] - mu) * rstd * sSc[h] + sOf[h];
    }
    __syncthreads();

    // ---- GEMM1: hid[128x32] = gelu(P @ Wh); 4 rows x 4 cols per thread ----
    // acc1[rp][c]: rowpair rp packs rows (rg1*4+2rp, +2rp+1), col cg1*4+c
    const int rg1 = t >> 3;          // 0..31 -> rows rg1*4..+3
    const int cg1 = t & 7;           // 0..7  -> cols cg1*4..+3
    float g16[2][2][4];              // [rp][parity][c] gelu'd hidden
    {
        unsigned long long acc1[2][4];
#pragma unroll
        for (int rp = 0; rp < 2; ++rp)
#pragma unroll
            for (int c = 0; c < 4; ++c) acc1[rp][c] = 0ull;

#pragma unroll
        for (int k = 0; k < HH; ++k) {
            const ulonglong2 A =
                *reinterpret_cast<const ulonglong2*>(&sP[k * SP + rg1 * 4]);
            const ulonglong2 B0 =
                *reinterpret_cast<const ulonglong2*>(&sWhD[k * 64 + cg1 * 8]);
            const ulonglong2 B1 =
                *reinterpret_cast<const ulonglong2*>(&sWhD[k * 64 + cg1 * 8 + 4]);
            fma2(acc1[0][0], A.x, B0.x); fma2(acc1[0][1], A.x, B0.y);
            fma2(acc1[0][2], A.x, B1.x); fma2(acc1[0][3], A.x, B1.y);
            fma2(acc1[1][0], A.y, B0.x); fma2(acc1[1][1], A.y, B0.y);
            fma2(acc1[1][2], A.y, B1.x); fma2(acc1[1][3], A.y, B1.y);
        }
#pragma unroll
        for (int rp = 0; rp < 2; ++rp)
#pragma unroll
            for (int c = 0; c < 4; ++c) {
                float2 v = up2(acc1[rp][c]);
                g16[rp][0][c] = gelu_tanh(v.x);
                g16[rp][1][c] = gelu_tanh(v.y);
            }
    }
    __syncthreads();   // everyone done reading sP (pair)

    // write hidden back into sP (K-major), aliased buffer
#pragma unroll
    for (int c = 0; c < 4; ++c) {
        *reinterpret_cast<float4*>(&sP[(cg1 * 4 + c) * SP + rg1 * 4]) =
            make_float4(g16[0][0][c], g16[0][1][c], g16[1][0][c], g16[1][1][c]);
    }
    __syncthreads();

    // ---- GEMM2: out[128x64] = hid @ Wo; 8 rows x 4 cols per thread ----
    {
        unsigned long long acc[4][4];   // [rowpair][col]
#pragma unroll
        for (int rp = 0; rp < 4; ++rp)
#pragma unroll
            for (int c = 0; c < 4; ++c) acc[rp][c] = 0ull;

#pragma unroll
        for (int k = 0; k < HH; ++k) {
            const ulonglong2 A0 =
                *reinterpret_cast<const ulonglong2*>(&sP[k * SP + rg2 * 8]);
            const ulonglong2 A1 =
                *reinterpret_cast<const ulonglong2*>(&sP[k * SP + rg2 * 8 + 4]);
            const ulonglong2 B0 =
                *reinterpret_cast<const ulonglong2*>(&sWoD[k * 128 + cg2 * 8]);
            const ulonglong2 B1 =
                *reinterpret_cast<const ulonglong2*>(&sWoD[k * 128 + cg2 * 8 + 4]);
            fma2(acc[0][0], A0.x, B0.x); fma2(acc[0][1], A0.x, B0.y);
            fma2(acc[0][2], A0.x, B1.x); fma2(acc[0][3], A0.x, B1.y);
            fma2(acc[1][0], A0.y, B0.x); fma2(acc[1][1], A0.y, B0.y);
            fma2(acc[1][2], A0.y, B1.x); fma2(acc[1][3], A0.y, B1.y);
            fma2(acc[2][0], A1.x, B0.x); fma2(acc[2][1], A1.x, B0.y);
            fma2(acc[2][2], A1.x, B1.x); fma2(acc[2][3], A1.x, B1.y);
            fma2(acc[3][0], A1.y, B0.x); fma2(acc[3][1], A1.y, B0.y);
            fma2(acc[3][2], A1.y, B1.x); fma2(acc[3][3], A1.y, B1.y);
        }

        // stores: row = rg2*8 + r8 -> i=i0+rg2, j=j0+r8; cols cg2*4..+3
        // lanes (cg2 = lane&15) cover contiguous 256B -> fully coalesced
        const float4 z = make_float4(0.f, 0.f, 0.f, 0.f);
        float* obase = out + ((size_t)((i0 + rg2) * NN + j0)) * OUTS + cg2 * 4;
#pragma unroll
        for (int rp = 0; rp < 4; ++rp) {
            float2 v0 = up2(acc[rp][0]), v1 = up2(acc[rp][1]);
            float2 v2 = up2(acc[rp][2]), v3 = up2(acc[rp][3]);
            float4* o0 = reinterpret_cast<float4*>(obase + (size_t)(2 * rp) * OUTS);
            float4* o1 = reinterpret_cast<float4*>(obase + (size_t)(2 * rp + 1) * OUTS);
            __stcs(o0, sPM[rg2 * 8 + 2 * rp]
                           ? make_float4(v0.x, v1.x, v2.x, v3.x) : z);
            __stcs(o1, sPM[rg2 * 8 + 2 * rp + 1]
                           ? make_float4(v0.y, v1.y, v2.y, v3.y) : z);
        }
    }
}

// ---------------------------------------------------------------------------
extern "C" void kernel_launch(void* const* d_in, const int* in_sizes, int n_in,
                              void* d_out, int out_size) {
    const float* local = (const float*)d_in[0];
    const int*   resi  = (const int*)d_in[1];
    const int*   chain = (const int*)d_in[2];
    const int*   batch = (const int*)d_in[3];
    const int*   mask  = (const int*)d_in[4];
    const float* Wl    = (const float*)d_in[5];
    const float* Wr    = (const float*)d_in[6];
    const float* Wrel  = (const float*)d_in[7];
    const float* lns   = (const float*)d_in[8];
    const float* lno   = (const float*)d_in[9];
    const float* Wh    = (const float*)d_in[10];
    const float* Wo    = (const float*)d_in[11];
    float*       out   = (float*)d_out;

    static bool attr_set = false;
    if (!attr_set) {
        cudaFuncSetAttribute(pair_kernel,
                             cudaFuncAttributeMaxDynamicSharedMemorySize,
                             SMEM_BYTES);
        attr_set = true;
    }

    proj_kernel<<<256, 256>>>(local, Wl, Wr);

    dim3 grid(NN / TJ, NN / TI);   // (128, 64)
    pair_kernel<<<grid, 256, SMEM_BYTES>>>(resi, chain, batch, mask, Wrel,
                                           lns, lno, Wh, Wo, out);
}